// round 12
// baseline (speedup 1.0000x reference)
#include <cuda_runtime.h>

// Problem constants (fixed shapes from reference)
#define BB 16
#define HH 512
#define WW 512
#define H2 1024
#define W2 1024
#define WV (W2 / 4)   // float4 vectors per output row

#define TOTAL_TILES (BB * HH * WV)   // 2,097,152 (2-row x 4-col tiles)
#define NUM_CTAS 592                 // 148 SMs x 4 CTAs/SM -> single wave

// Fused: bilinear 2x upsample of mask (2ch) -> x_mask,y_mask;
// fused_c = xm*xl_c + ym*yl_c; out_o = relu(sum_i w[o,i]*fused_i + b_o).
// R11: persistent grid-stride version of R9 (2-row x 4-col tile, 64 regs,
// 4 CTA/SM). One wave of 592 CTAs, each thread loops ~14 tiles -> no
// wave-transition bubbles, naturally desynced warps smooth DRAM rw mix.
__global__ void __launch_bounds__(256, 4) fused_upsample_blend_conv_kernel(
    const float* __restrict__ mask,   // (B,2,H,W)
    const float* __restrict__ xl,     // (B,3,H2,W2)
    const float* __restrict__ yl,     // (B,3,H2,W2)
    const float* __restrict__ cw,     // (3,3) row-major 'oi'
    const float* __restrict__ cb,     // (3,)
    float* __restrict__ out)          // (B,3,H2,W2) ++ (B,1,H2,W2) ++ (B,1,H2,W2)
{
    // conv weights / bias: loop-invariant, load once
    const float w00 = __ldg(cw + 0), w01 = __ldg(cw + 1), w02 = __ldg(cw + 2);
    const float w10 = __ldg(cw + 3), w11 = __ldg(cw + 4), w12 = __ldg(cw + 5);
    const float w20 = __ldg(cw + 6), w21 = __ldg(cw + 7), w22 = __ldg(cw + 8);
    const float b0 = __ldg(cb + 0), b1 = __ldg(cb + 1), b2 = __ldg(cb + 2);

    const size_t plane = (size_t)H2 * W2;
    float* out_main = out;                                   // (B,3,H2,W2)
    float* out_xm   = out + (size_t)BB * 3 * plane;          // (B,1,H2,W2)
    float* out_ym   = out_xm + (size_t)BB * plane;           // (B,1,H2,W2)

    const int stride = gridDim.x * blockDim.x;

    for (int idx = blockIdx.x * blockDim.x + threadIdx.x; idx < TOTAL_TILES; idx += stride) {
        int ox4 = idx & (WV - 1);        // vector index along width
        int t   = idx >> 8;              // WV = 256
        int k   = t & (HH - 1);          // input row / output row-pair index
        int b   = t >> 9;                // HH = 512

        // ---- stream loads FIRST: 2 rows x 3 channels x 2 tensors = 12 float4 ----
        const int oy0 = 2 * k;
        const size_t base0 = (size_t)b * 3 * plane + (size_t)oy0 * W2 + (size_t)ox4 * 4;
        const size_t base1 = base0 + W2;   // odd row

        float4 xe0 = *(const float4*)(xl + base0);
        float4 xe1 = *(const float4*)(xl + base0 + plane);
        float4 xe2 = *(const float4*)(xl + base0 + 2 * plane);
        float4 xo0 = *(const float4*)(xl + base1);
        float4 xo1 = *(const float4*)(xl + base1 + plane);
        float4 xo2 = *(const float4*)(xl + base1 + 2 * plane);
        float4 ye0 = *(const float4*)(yl + base0);
        float4 ye1 = *(const float4*)(yl + base0 + plane);
        float4 ye2 = *(const float4*)(yl + base0 + 2 * plane);
        float4 yo0 = *(const float4*)(yl + base1);
        float4 yo1 = *(const float4*)(yl + base1 + plane);
        float4 yo2 = *(const float4*)(yl + base1 + 2 * plane);

        // ---- mask loads (mostly L2 hits) ----
        int km1 = k - 1; if (km1 < 0) km1 = 0;
        int kp1 = k + 1; if (kp1 > HH - 1) kp1 = HH - 1;

        int m   = ox4 * 2;                       // 0..510, even
        int cm1 = m - 1; if (cm1 < 0) cm1 = 0;
        int cp1 = m + 1;                         // <= 511 always
        int cp2 = m + 2; if (cp2 > WW - 1) cp2 = WW - 1;

        const size_t mplane = (size_t)HH * WW;
        const float* mx = mask + ((size_t)b * 2 + 0) * mplane;
        const float* my = mask + ((size_t)b * 2 + 1) * mplane;
        const float* mx_m = mx + (size_t)km1 * WW;
        const float* mx_0 = mx + (size_t)k   * WW;
        const float* mx_p = mx + (size_t)kp1 * WW;
        const float* my_m = my + (size_t)km1 * WW;
        const float* my_0 = my + (size_t)k   * WW;
        const float* my_p = my + (size_t)kp1 * WW;

        float xA0 = __ldg(mx_m + cm1), xA1 = __ldg(mx_m + m), xA2 = __ldg(mx_m + cp1), xA3 = __ldg(mx_m + cp2);
        float xB0 = __ldg(mx_0 + cm1), xB1 = __ldg(mx_0 + m), xB2 = __ldg(mx_0 + cp1), xB3 = __ldg(mx_0 + cp2);
        float xC0 = __ldg(mx_p + cm1), xC1 = __ldg(mx_p + m), xC2 = __ldg(mx_p + cp1), xC3 = __ldg(mx_p + cp2);
        float yA0 = __ldg(my_m + cm1), yA1 = __ldg(my_m + m), yA2 = __ldg(my_m + cp1), yA3 = __ldg(my_m + cp2);
        float yB0 = __ldg(my_0 + cm1), yB1 = __ldg(my_0 + m), yB2 = __ldg(my_0 + cp1), yB3 = __ldg(my_0 + cp2);
        float yC0 = __ldg(my_p + cm1), yC1 = __ldg(my_p + m), yC2 = __ldg(my_p + cp1), yC3 = __ldg(my_p + cp2);

        // vertical interpolation per input column, for even (e) and odd (o) rows
        float vxe0 = 0.25f*xA0 + 0.75f*xB0, vxe1 = 0.25f*xA1 + 0.75f*xB1;
        float vxe2 = 0.25f*xA2 + 0.75f*xB2, vxe3 = 0.25f*xA3 + 0.75f*xB3;
        float vxo0 = 0.75f*xB0 + 0.25f*xC0, vxo1 = 0.75f*xB1 + 0.25f*xC1;
        float vxo2 = 0.75f*xB2 + 0.25f*xC2, vxo3 = 0.75f*xB3 + 0.25f*xC3;
        float vye0 = 0.25f*yA0 + 0.75f*yB0, vye1 = 0.25f*yA1 + 0.75f*yB1;
        float vye2 = 0.25f*yA2 + 0.75f*yB2, vye3 = 0.25f*yA3 + 0.75f*yB3;
        float vyo0 = 0.75f*yB0 + 0.25f*yC0, vyo1 = 0.75f*yB1 + 0.25f*yC1;
        float vyo2 = 0.75f*yB2 + 0.25f*yC2, vyo3 = 0.75f*yB3 + 0.25f*yC3;

        // horizontal combine -> per-row 4-wide masks
        float xme[4], xmo[4], yme[4], ymo[4];
        xme[0] = 0.25f*vxe0 + 0.75f*vxe1;  xme[1] = 0.75f*vxe1 + 0.25f*vxe2;
        xme[2] = 0.25f*vxe1 + 0.75f*vxe2;  xme[3] = 0.75f*vxe2 + 0.25f*vxe3;
        xmo[0] = 0.25f*vxo0 + 0.75f*vxo1;  xmo[1] = 0.75f*vxo1 + 0.25f*vxo2;
        xmo[2] = 0.25f*vxo1 + 0.75f*vxo2;  xmo[3] = 0.75f*vxo2 + 0.25f*vxo3;
        yme[0] = 0.25f*vye0 + 0.75f*vye1;  yme[1] = 0.75f*vye1 + 0.25f*vye2;
        yme[2] = 0.25f*vye1 + 0.75f*vye2;  yme[3] = 0.75f*vye2 + 0.25f*vye3;
        ymo[0] = 0.25f*vyo0 + 0.75f*vyo1;  ymo[1] = 0.75f*vyo1 + 0.25f*vyo2;
        ymo[2] = 0.25f*vyo1 + 0.75f*vyo2;  ymo[3] = 0.75f*vyo2 + 0.25f*vyo3;

        // ---- per-row: blend, channel-mix, relu, store ----
        #pragma unroll
        for (int r = 0; r < 2; r++) {
            const float* xm = r ? xmo : xme;
            const float* ym = r ? ymo : yme;
            float4 c0 = r ? xo0 : xe0, c1 = r ? xo1 : xe1, c2 = r ? xo2 : xe2;
            float4 d0 = r ? yo0 : ye0, d1 = r ? yo1 : ye1, d2 = r ? yo2 : ye2;
            size_t base = r ? base1 : base0;

            float f0[4] = { xm[0]*c0.x + ym[0]*d0.x, xm[1]*c0.y + ym[1]*d0.y,
                            xm[2]*c0.z + ym[2]*d0.z, xm[3]*c0.w + ym[3]*d0.w };
            float f1[4] = { xm[0]*c1.x + ym[0]*d1.x, xm[1]*c1.y + ym[1]*d1.y,
                            xm[2]*c1.z + ym[2]*d1.z, xm[3]*c1.w + ym[3]*d1.w };
            float f2[4] = { xm[0]*c2.x + ym[0]*d2.x, xm[1]*c2.y + ym[1]*d2.y,
                            xm[2]*c2.z + ym[2]*d2.z, xm[3]*c2.w + ym[3]*d2.w };

            float4 o0, o1, o2;
            {
                float rr[4];
                #pragma unroll
                for (int q = 0; q < 4; q++) {
                    float v = w00 * f0[q] + w01 * f1[q] + w02 * f2[q] + b0;
                    rr[q] = v > 0.0f ? v : 0.0f;
                }
                o0 = make_float4(rr[0], rr[1], rr[2], rr[3]);
                #pragma unroll
                for (int q = 0; q < 4; q++) {
                    float v = w10 * f0[q] + w11 * f1[q] + w12 * f2[q] + b1;
                    rr[q] = v > 0.0f ? v : 0.0f;
                }
                o1 = make_float4(rr[0], rr[1], rr[2], rr[3]);
                #pragma unroll
                for (int q = 0; q < 4; q++) {
                    float v = w20 * f0[q] + w21 * f1[q] + w22 * f2[q] + b2;
                    rr[q] = v > 0.0f ? v : 0.0f;
                }
                o2 = make_float4(rr[0], rr[1], rr[2], rr[3]);
            }

            *(float4*)(out_main + base)             = o0;
            *(float4*)(out_main + base + plane)     = o1;
            *(float4*)(out_main + base + 2 * plane) = o2;

            size_t mbase = (size_t)b * plane + (size_t)(oy0 + r) * W2 + (size_t)ox4 * 4;
            *(float4*)(out_xm + mbase) = make_float4(xm[0], xm[1], xm[2], xm[3]);
            *(float4*)(out_ym + mbase) = make_float4(ym[0], ym[1], ym[2], ym[3]);
        }
    }
}

extern "C" void kernel_launch(void* const* d_in, const int* in_sizes, int n_in,
                              void* d_out, int out_size) {
    const float* mask = (const float*)d_in[0];
    const float* xl   = (const float*)d_in[1];
    const float* yl   = (const float*)d_in[2];
    const float* cw   = (const float*)d_in[3];
    const float* cb   = (const float*)d_in[4];
    float* out = (float*)d_out;

    fused_upsample_blend_conv_kernel<<<NUM_CTAS, 256>>>(mask, xl, yl, cw, cb, out);
}

// round 13
// speedup vs baseline: 1.1095x; 1.1095x over previous
#include <cuda_runtime.h>

// Problem constants (fixed shapes from reference)
#define BB 16
#define HH 512
#define WW 512
#define H2 1024
#define W2 1024
#define WV (W2 / 4)   // float4 vectors per output row

// Fused: bilinear 2x upsample of mask (2ch) -> x_mask,y_mask;
// fused_c = xm*xl_c + ym*yl_c; out_o = relu(sum_i w[o,i]*fused_i + b_o).
// R13: R10 body (2-row x 4-col tile, 12 front-batched LDG.128, 64-reg cap)
// at 128 threads/CTA x 8 CTAs/SM: same resident warps, finer tail granularity.
__global__ void __launch_bounds__(128, 8) fused_upsample_blend_conv_kernel(
    const float* __restrict__ mask,   // (B,2,H,W)
    const float* __restrict__ xl,     // (B,3,H2,W2)
    const float* __restrict__ yl,     // (B,3,H2,W2)
    const float* __restrict__ cw,     // (3,3) row-major 'oi'
    const float* __restrict__ cb,     // (3,)
    float* __restrict__ out)          // (B,3,H2,W2) ++ (B,1,H2,W2) ++ (B,1,H2,W2)
{
    int idx = blockIdx.x * blockDim.x + threadIdx.x;
    int ox4 = idx & (WV - 1);        // vector index along width
    int t   = idx >> 8;              // WV = 256
    int k   = t & (HH - 1);          // input row / output row-pair index
    int b   = t >> 9;                // HH = 512
    if (b >= BB) return;

    // ---- stream loads FIRST: 2 rows x 3 channels x 2 tensors = 12 float4 ----
    const size_t plane = (size_t)H2 * W2;
    const int oy0 = 2 * k;
    const size_t base0 = (size_t)b * 3 * plane + (size_t)oy0 * W2 + (size_t)ox4 * 4;
    const size_t base1 = base0 + W2;   // odd row

    float4 xe0 = *(const float4*)(xl + base0);
    float4 xe1 = *(const float4*)(xl + base0 + plane);
    float4 xe2 = *(const float4*)(xl + base0 + 2 * plane);
    float4 xo0 = *(const float4*)(xl + base1);
    float4 xo1 = *(const float4*)(xl + base1 + plane);
    float4 xo2 = *(const float4*)(xl + base1 + 2 * plane);
    float4 ye0 = *(const float4*)(yl + base0);
    float4 ye1 = *(const float4*)(yl + base0 + plane);
    float4 ye2 = *(const float4*)(yl + base0 + 2 * plane);
    float4 yo0 = *(const float4*)(yl + base1);
    float4 yo1 = *(const float4*)(yl + base1 + plane);
    float4 yo2 = *(const float4*)(yl + base1 + 2 * plane);

    // ---- mask loads second (mostly L2 hits) ----
    int km1 = k - 1; if (km1 < 0) km1 = 0;
    int kp1 = k + 1; if (kp1 > HH - 1) kp1 = HH - 1;

    int m   = ox4 * 2;                       // 0..510, even
    int cm1 = m - 1; if (cm1 < 0) cm1 = 0;
    int cp1 = m + 1;                         // <= 511 always
    int cp2 = m + 2; if (cp2 > WW - 1) cp2 = WW - 1;

    const size_t mplane = (size_t)HH * WW;
    const float* mx = mask + ((size_t)b * 2 + 0) * mplane;
    const float* my = mask + ((size_t)b * 2 + 1) * mplane;
    const float* mx_m = mx + (size_t)km1 * WW;
    const float* mx_0 = mx + (size_t)k   * WW;
    const float* mx_p = mx + (size_t)kp1 * WW;
    const float* my_m = my + (size_t)km1 * WW;
    const float* my_0 = my + (size_t)k   * WW;
    const float* my_p = my + (size_t)kp1 * WW;

    float xA0 = __ldg(mx_m + cm1), xA1 = __ldg(mx_m + m), xA2 = __ldg(mx_m + cp1), xA3 = __ldg(mx_m + cp2);
    float xB0 = __ldg(mx_0 + cm1), xB1 = __ldg(mx_0 + m), xB2 = __ldg(mx_0 + cp1), xB3 = __ldg(mx_0 + cp2);
    float xC0 = __ldg(mx_p + cm1), xC1 = __ldg(mx_p + m), xC2 = __ldg(mx_p + cp1), xC3 = __ldg(mx_p + cp2);
    float yA0 = __ldg(my_m + cm1), yA1 = __ldg(my_m + m), yA2 = __ldg(my_m + cp1), yA3 = __ldg(my_m + cp2);
    float yB0 = __ldg(my_0 + cm1), yB1 = __ldg(my_0 + m), yB2 = __ldg(my_0 + cp1), yB3 = __ldg(my_0 + cp2);
    float yC0 = __ldg(my_p + cm1), yC1 = __ldg(my_p + m), yC2 = __ldg(my_p + cp1), yC3 = __ldg(my_p + cp2);

    // vertical interpolation per input column, for even (e) and odd (o) rows
    float vxe0 = 0.25f*xA0 + 0.75f*xB0, vxe1 = 0.25f*xA1 + 0.75f*xB1;
    float vxe2 = 0.25f*xA2 + 0.75f*xB2, vxe3 = 0.25f*xA3 + 0.75f*xB3;
    float vxo0 = 0.75f*xB0 + 0.25f*xC0, vxo1 = 0.75f*xB1 + 0.25f*xC1;
    float vxo2 = 0.75f*xB2 + 0.25f*xC2, vxo3 = 0.75f*xB3 + 0.25f*xC3;
    float vye0 = 0.25f*yA0 + 0.75f*yB0, vye1 = 0.25f*yA1 + 0.75f*yB1;
    float vye2 = 0.25f*yA2 + 0.75f*yB2, vye3 = 0.25f*yA3 + 0.75f*yB3;
    float vyo0 = 0.75f*yB0 + 0.25f*yC0, vyo1 = 0.75f*yB1 + 0.25f*yC1;
    float vyo2 = 0.75f*yB2 + 0.25f*yC2, vyo3 = 0.75f*yB3 + 0.25f*yC3;

    // horizontal combine -> per-row 4-wide masks
    float xme[4], xmo[4], yme[4], ymo[4];
    xme[0] = 0.25f*vxe0 + 0.75f*vxe1;  xme[1] = 0.75f*vxe1 + 0.25f*vxe2;
    xme[2] = 0.25f*vxe1 + 0.75f*vxe2;  xme[3] = 0.75f*vxe2 + 0.25f*vxe3;
    xmo[0] = 0.25f*vxo0 + 0.75f*vxo1;  xmo[1] = 0.75f*vxo1 + 0.25f*vxo2;
    xmo[2] = 0.25f*vxo1 + 0.75f*vxo2;  xmo[3] = 0.75f*vxo2 + 0.25f*vxo3;
    yme[0] = 0.25f*vye0 + 0.75f*vye1;  yme[1] = 0.75f*vye1 + 0.25f*vye2;
    yme[2] = 0.25f*vye1 + 0.75f*vye2;  yme[3] = 0.75f*vye2 + 0.25f*vye3;
    ymo[0] = 0.25f*vyo0 + 0.75f*vyo1;  ymo[1] = 0.75f*vyo1 + 0.25f*vyo2;
    ymo[2] = 0.25f*vyo1 + 0.75f*vyo2;  ymo[3] = 0.75f*vyo2 + 0.25f*vyo3;

    // conv weights / bias
    float w00 = __ldg(cw + 0), w01 = __ldg(cw + 1), w02 = __ldg(cw + 2);
    float w10 = __ldg(cw + 3), w11 = __ldg(cw + 4), w12 = __ldg(cw + 5);
    float w20 = __ldg(cw + 6), w21 = __ldg(cw + 7), w22 = __ldg(cw + 8);
    float b0 = __ldg(cb + 0), b1 = __ldg(cb + 1), b2 = __ldg(cb + 2);

    float* out_main = out;                                   // (B,3,H2,W2)
    float* out_xm   = out + (size_t)BB * 3 * plane;          // (B,1,H2,W2)
    float* out_ym   = out_xm + (size_t)BB * plane;           // (B,1,H2,W2)

    // ---- per-row: blend, channel-mix, relu, store ----
    #pragma unroll
    for (int r = 0; r < 2; r++) {
        const float* xm = r ? xmo : xme;
        const float* ym = r ? ymo : yme;
        float4 c0 = r ? xo0 : xe0, c1 = r ? xo1 : xe1, c2 = r ? xo2 : xe2;
        float4 d0 = r ? yo0 : ye0, d1 = r ? yo1 : ye1, d2 = r ? yo2 : ye2;
        size_t base = r ? base1 : base0;

        float f0[4] = { xm[0]*c0.x + ym[0]*d0.x, xm[1]*c0.y + ym[1]*d0.y,
                        xm[2]*c0.z + ym[2]*d0.z, xm[3]*c0.w + ym[3]*d0.w };
        float f1[4] = { xm[0]*c1.x + ym[0]*d1.x, xm[1]*c1.y + ym[1]*d1.y,
                        xm[2]*c1.z + ym[2]*d1.z, xm[3]*c1.w + ym[3]*d1.w };
        float f2[4] = { xm[0]*c2.x + ym[0]*d2.x, xm[1]*c2.y + ym[1]*d2.y,
                        xm[2]*c2.z + ym[2]*d2.z, xm[3]*c2.w + ym[3]*d2.w };

        float4 o0, o1, o2;
        {
            float rr[4];
            #pragma unroll
            for (int q = 0; q < 4; q++) {
                float v = w00 * f0[q] + w01 * f1[q] + w02 * f2[q] + b0;
                rr[q] = v > 0.0f ? v : 0.0f;
            }
            o0 = make_float4(rr[0], rr[1], rr[2], rr[3]);
            #pragma unroll
            for (int q = 0; q < 4; q++) {
                float v = w10 * f0[q] + w11 * f1[q] + w12 * f2[q] + b1;
                rr[q] = v > 0.0f ? v : 0.0f;
            }
            o1 = make_float4(rr[0], rr[1], rr[2], rr[3]);
            #pragma unroll
            for (int q = 0; q < 4; q++) {
                float v = w20 * f0[q] + w21 * f1[q] + w22 * f2[q] + b2;
                rr[q] = v > 0.0f ? v : 0.0f;
            }
            o2 = make_float4(rr[0], rr[1], rr[2], rr[3]);
        }

        *(float4*)(out_main + base)             = o0;
        *(float4*)(out_main + base + plane)     = o1;
        *(float4*)(out_main + base + 2 * plane) = o2;

        size_t mbase = (size_t)b * plane + (size_t)(oy0 + r) * W2 + (size_t)ox4 * 4;
        *(float4*)(out_xm + mbase) = make_float4(xm[0], xm[1], xm[2], xm[3]);
        *(float4*)(out_ym + mbase) = make_float4(ym[0], ym[1], ym[2], ym[3]);
    }
}

extern "C" void kernel_launch(void* const* d_in, const int* in_sizes, int n_in,
                              void* d_out, int out_size) {
    const float* mask = (const float*)d_in[0];
    const float* xl   = (const float*)d_in[1];
    const float* yl   = (const float*)d_in[2];
    const float* cw   = (const float*)d_in[3];
    const float* cb   = (const float*)d_in[4];
    float* out = (float*)d_out;

    const int total = BB * HH * WV;          // 2,097,152 threads (2 rows each)
    const int threads = 128;
    const int blocks = (total + threads - 1) / threads;   // 16384
    fused_upsample_blend_conv_kernel<<<blocks, threads>>>(mask, xl, yl, cw, cb, out);
}

// round 14
// speedup vs baseline: 1.1132x; 1.0033x over previous
#include <cuda_runtime.h>

// Problem constants (fixed shapes from reference)
#define BB 16
#define HH 512
#define WW 512
#define H2 1024
#define W2 1024
#define WV (W2 / 4)   // float4 vectors per output row

// Fused: bilinear 2x upsample of mask (2ch) -> x_mask,y_mask;
// fused_c = xm*xl_c + ym*yl_c; out_o = relu(sum_i w[o,i]*fused_i + b_o).
// R14: R13 (2-row x 4-col tile, 128thr x 8 CTA/SM, 64-reg cap, stream loads
// first) + middle mask pair {m, m+1} loaded as one aligned float2 per row:
// mask LDG requests per thread 24 -> 18.
__global__ void __launch_bounds__(128, 8) fused_upsample_blend_conv_kernel(
    const float* __restrict__ mask,   // (B,2,H,W)
    const float* __restrict__ xl,     // (B,3,H2,W2)
    const float* __restrict__ yl,     // (B,3,H2,W2)
    const float* __restrict__ cw,     // (3,3) row-major 'oi'
    const float* __restrict__ cb,     // (3,)
    float* __restrict__ out)          // (B,3,H2,W2) ++ (B,1,H2,W2) ++ (B,1,H2,W2)
{
    int idx = blockIdx.x * blockDim.x + threadIdx.x;
    int ox4 = idx & (WV - 1);        // vector index along width
    int t   = idx >> 8;              // WV = 256
    int k   = t & (HH - 1);          // input row / output row-pair index
    int b   = t >> 9;                // HH = 512
    if (b >= BB) return;

    // ---- stream loads FIRST: 2 rows x 3 channels x 2 tensors = 12 float4 ----
    const size_t plane = (size_t)H2 * W2;
    const int oy0 = 2 * k;
    const size_t base0 = (size_t)b * 3 * plane + (size_t)oy0 * W2 + (size_t)ox4 * 4;
    const size_t base1 = base0 + W2;   // odd row

    float4 xe0 = *(const float4*)(xl + base0);
    float4 xe1 = *(const float4*)(xl + base0 + plane);
    float4 xe2 = *(const float4*)(xl + base0 + 2 * plane);
    float4 xo0 = *(const float4*)(xl + base1);
    float4 xo1 = *(const float4*)(xl + base1 + plane);
    float4 xo2 = *(const float4*)(xl + base1 + 2 * plane);
    float4 ye0 = *(const float4*)(yl + base0);
    float4 ye1 = *(const float4*)(yl + base0 + plane);
    float4 ye2 = *(const float4*)(yl + base0 + 2 * plane);
    float4 yo0 = *(const float4*)(yl + base1);
    float4 yo1 = *(const float4*)(yl + base1 + plane);
    float4 yo2 = *(const float4*)(yl + base1 + 2 * plane);

    // ---- mask loads second (mostly L2 hits) ----
    int km1 = k - 1; if (km1 < 0) km1 = 0;
    int kp1 = k + 1; if (kp1 > HH - 1) kp1 = HH - 1;

    int m   = ox4 * 2;                       // 0..510, even -> (mx + m) is 8B-aligned
    int cm1 = m - 1; if (cm1 < 0) cm1 = 0;
    int cp2 = m + 2; if (cp2 > WW - 1) cp2 = WW - 1;

    const size_t mplane = (size_t)HH * WW;
    const float* mx = mask + ((size_t)b * 2 + 0) * mplane;
    const float* my = mask + ((size_t)b * 2 + 1) * mplane;
    const float* mx_m = mx + (size_t)km1 * WW;
    const float* mx_0 = mx + (size_t)k   * WW;
    const float* mx_p = mx + (size_t)kp1 * WW;
    const float* my_m = my + (size_t)km1 * WW;
    const float* my_0 = my + (size_t)k   * WW;
    const float* my_p = my + (size_t)kp1 * WW;

    // middle pair {m, m+1} as float2, edges scalar: 3 requests per row
    float2 pxA = *(const float2*)(mx_m + m);
    float2 pxB = *(const float2*)(mx_0 + m);
    float2 pxC = *(const float2*)(mx_p + m);
    float2 pyA = *(const float2*)(my_m + m);
    float2 pyB = *(const float2*)(my_0 + m);
    float2 pyC = *(const float2*)(my_p + m);

    float xA0 = __ldg(mx_m + cm1), xA3 = __ldg(mx_m + cp2);
    float xB0 = __ldg(mx_0 + cm1), xB3 = __ldg(mx_0 + cp2);
    float xC0 = __ldg(mx_p + cm1), xC3 = __ldg(mx_p + cp2);
    float yA0 = __ldg(my_m + cm1), yA3 = __ldg(my_m + cp2);
    float yB0 = __ldg(my_0 + cm1), yB3 = __ldg(my_0 + cp2);
    float yC0 = __ldg(my_p + cm1), yC3 = __ldg(my_p + cp2);

    float xA1 = pxA.x, xA2 = pxA.y;
    float xB1 = pxB.x, xB2 = pxB.y;
    float xC1 = pxC.x, xC2 = pxC.y;
    float yA1 = pyA.x, yA2 = pyA.y;
    float yB1 = pyB.x, yB2 = pyB.y;
    float yC1 = pyC.x, yC2 = pyC.y;

    // vertical interpolation per input column, for even (e) and odd (o) rows
    float vxe0 = 0.25f*xA0 + 0.75f*xB0, vxe1 = 0.25f*xA1 + 0.75f*xB1;
    float vxe2 = 0.25f*xA2 + 0.75f*xB2, vxe3 = 0.25f*xA3 + 0.75f*xB3;
    float vxo0 = 0.75f*xB0 + 0.25f*xC0, vxo1 = 0.75f*xB1 + 0.25f*xC1;
    float vxo2 = 0.75f*xB2 + 0.25f*xC2, vxo3 = 0.75f*xB3 + 0.25f*xC3;
    float vye0 = 0.25f*yA0 + 0.75f*yB0, vye1 = 0.25f*yA1 + 0.75f*yB1;
    float vye2 = 0.25f*yA2 + 0.75f*yB2, vye3 = 0.25f*yA3 + 0.75f*yB3;
    float vyo0 = 0.75f*yB0 + 0.25f*yC0, vyo1 = 0.75f*yB1 + 0.25f*yC1;
    float vyo2 = 0.75f*yB2 + 0.25f*yC2, vyo3 = 0.75f*yB3 + 0.25f*yC3;

    // horizontal combine -> per-row 4-wide masks
    float xme[4], xmo[4], yme[4], ymo[4];
    xme[0] = 0.25f*vxe0 + 0.75f*vxe1;  xme[1] = 0.75f*vxe1 + 0.25f*vxe2;
    xme[2] = 0.25f*vxe1 + 0.75f*vxe2;  xme[3] = 0.75f*vxe2 + 0.25f*vxe3;
    xmo[0] = 0.25f*vxo0 + 0.75f*vxo1;  xmo[1] = 0.75f*vxo1 + 0.25f*vxo2;
    xmo[2] = 0.25f*vxo1 + 0.75f*vxo2;  xmo[3] = 0.75f*vxo2 + 0.25f*vxo3;
    yme[0] = 0.25f*vye0 + 0.75f*vye1;  yme[1] = 0.75f*vye1 + 0.25f*vye2;
    yme[2] = 0.25f*vye1 + 0.75f*vye2;  yme[3] = 0.75f*vye2 + 0.25f*vye3;
    ymo[0] = 0.25f*vyo0 + 0.75f*vyo1;  ymo[1] = 0.75f*vyo1 + 0.25f*vyo2;
    ymo[2] = 0.25f*vyo1 + 0.75f*vyo2;  ymo[3] = 0.75f*vyo2 + 0.25f*vyo3;

    // conv weights / bias
    float w00 = __ldg(cw + 0), w01 = __ldg(cw + 1), w02 = __ldg(cw + 2);
    float w10 = __ldg(cw + 3), w11 = __ldg(cw + 4), w12 = __ldg(cw + 5);
    float w20 = __ldg(cw + 6), w21 = __ldg(cw + 7), w22 = __ldg(cw + 8);
    float b0 = __ldg(cb + 0), b1 = __ldg(cb + 1), b2 = __ldg(cb + 2);

    float* out_main = out;                                   // (B,3,H2,W2)
    float* out_xm   = out + (size_t)BB * 3 * plane;          // (B,1,H2,W2)
    float* out_ym   = out_xm + (size_t)BB * plane;           // (B,1,H2,W2)

    // ---- per-row: blend, channel-mix, relu, store ----
    #pragma unroll
    for (int r = 0; r < 2; r++) {
        const float* xm = r ? xmo : xme;
        const float* ym = r ? ymo : yme;
        float4 c0 = r ? xo0 : xe0, c1 = r ? xo1 : xe1, c2 = r ? xo2 : xe2;
        float4 d0 = r ? yo0 : ye0, d1 = r ? yo1 : ye1, d2 = r ? yo2 : ye2;
        size_t base = r ? base1 : base0;

        float f0[4] = { xm[0]*c0.x + ym[0]*d0.x, xm[1]*c0.y + ym[1]*d0.y,
                        xm[2]*c0.z + ym[2]*d0.z, xm[3]*c0.w + ym[3]*d0.w };
        float f1[4] = { xm[0]*c1.x + ym[0]*d1.x, xm[1]*c1.y + ym[1]*d1.y,
                        xm[2]*c1.z + ym[2]*d1.z, xm[3]*c1.w + ym[3]*d1.w };
        float f2[4] = { xm[0]*c2.x + ym[0]*d2.x, xm[1]*c2.y + ym[1]*d2.y,
                        xm[2]*c2.z + ym[2]*d2.z, xm[3]*c2.w + ym[3]*d2.w };

        float4 o0, o1, o2;
        {
            float rr[4];
            #pragma unroll
            for (int q = 0; q < 4; q++) {
                float v = w00 * f0[q] + w01 * f1[q] + w02 * f2[q] + b0;
                rr[q] = v > 0.0f ? v : 0.0f;
            }
            o0 = make_float4(rr[0], rr[1], rr[2], rr[3]);
            #pragma unroll
            for (int q = 0; q < 4; q++) {
                float v = w10 * f0[q] + w11 * f1[q] + w12 * f2[q] + b1;
                rr[q] = v > 0.0f ? v : 0.0f;
            }
            o1 = make_float4(rr[0], rr[1], rr[2], rr[3]);
            #pragma unroll
            for (int q = 0; q < 4; q++) {
                float v = w20 * f0[q] + w21 * f1[q] + w22 * f2[q] + b2;
                rr[q] = v > 0.0f ? v : 0.0f;
            }
            o2 = make_float4(rr[0], rr[1], rr[2], rr[3]);
        }

        *(float4*)(out_main + base)             = o0;
        *(float4*)(out_main + base + plane)     = o1;
        *(float4*)(out_main + base + 2 * plane) = o2;

        size_t mbase = (size_t)b * plane + (size_t)(oy0 + r) * W2 + (size_t)ox4 * 4;
        *(float4*)(out_xm + mbase) = make_float4(xm[0], xm[1], xm[2], xm[3]);
        *(float4*)(out_ym + mbase) = make_float4(ym[0], ym[1], ym[2], ym[3]);
    }
}

extern "C" void kernel_launch(void* const* d_in, const int* in_sizes, int n_in,
                              void* d_out, int out_size) {
    const float* mask = (const float*)d_in[0];
    const float* xl   = (const float*)d_in[1];
    const float* yl   = (const float*)d_in[2];
    const float* cw   = (const float*)d_in[3];
    const float* cb   = (const float*)d_in[4];
    float* out = (float*)d_out;

    const int total = BB * HH * WV;          // 2,097,152 threads (2 rows each)
    const int threads = 128;
    const int blocks = (total + threads - 1) / threads;   // 16384
    fused_upsample_blend_conv_kernel<<<blocks, threads>>>(mask, xl, yl, cw, cb, out);
}